// round 6
// baseline (speedup 1.0000x reference)
#include <cuda_runtime.h>
#include <cuda_bf16.h>
#include <cstdint>

#define NN 50000
#define NE 800000
#define D  64
#define DK 128
#define CAP 96
#define HT_STRIDE 132

// Statically zero-initialized; fused_kernel resets each node's counter to 0
// after use, so every replay of the captured graph sees zeros again.
__device__ int g_deg_i[NN];
__device__ int g_slot[(size_t)NN * CAP];   // src ids bucketed by dst, padded rows

// ---------------------------------------------------------------------------
// Kernel 1: bucket fill. 4 edges per thread via int4 loads.
// ---------------------------------------------------------------------------
__global__ __launch_bounds__(256) void fill_kernel(const int* __restrict__ src,
                                                   const int* __restrict__ dst) {
    int q = blockIdx.x * blockDim.x + threadIdx.x;     // quad index
    if (q >= NE / 4) return;                            // NE divisible by 4
    int4 s4 = ((const int4*)src)[q];
    int4 d4 = ((const int4*)dst)[q];
    int pos;
    pos = atomicAdd(&g_deg_i[d4.x], 1); if (pos < CAP) g_slot[(size_t)d4.x * CAP + pos] = s4.x;
    pos = atomicAdd(&g_deg_i[d4.y], 1); if (pos < CAP) g_slot[(size_t)d4.y * CAP + pos] = s4.y;
    pos = atomicAdd(&g_deg_i[d4.z], 1); if (pos < CAP) g_slot[(size_t)d4.z * CAP + pos] = s4.z;
    pos = atomicAdd(&g_deg_i[d4.w], 1); if (pos < CAP) g_slot[(size_t)d4.w * CAP + pos] = s4.w;
}

// ---------------------------------------------------------------------------
// Kernel 2: fused gather + GEMM.
// Block = 256 threads = 64 nodes. Phase A: 8 warps gather 8 nodes each into
// ht (register accumulate, unroll-8 for 16 loads in flight). Resets g_deg_i.
// Phase B: 4x4 micro-tile GEMM, W staged in shared.
// ---------------------------------------------------------------------------
__global__ __launch_bounds__(256) void fused_kernel(const float* __restrict__ h,
                                                    const float* __restrict__ W,
                                                    const float* __restrict__ b,
                                                    float* __restrict__ out) {
    __shared__ float Ws[DK * D];          // 32 KB
    __shared__ float ht[64][HT_STRIDE];   // ~33.8 KB

    int t = threadIdx.x;
    int base = blockIdx.x * 64;
    int warp = t >> 5;
    int lane = t & 31;

    // Stage W (2048 float4 by 256 threads)
    {
        const float4* Wv = (const float4*)W;
        float4* Wsv = (float4*)Ws;
        #pragma unroll
        for (int i = 0; i < 8; i++) Wsv[t + i * 256] = Wv[t + i * 256];
    }

    // Phase A: gather. Warp w handles nodes base + w*8 .. +7.
    #pragma unroll 1
    for (int i = 0; i < 8; i++) {
        int m = warp * 8 + i;
        int node = base + m;
        if (node >= NN) break;

        // self features
        const float* hrow = h + (size_t)node * D;
        ht[m][lane]      = hrow[lane];
        ht[m][lane + 32] = hrow[lane + 32];

        int dg  = g_deg_i[node];
        if (lane == 0) g_deg_i[node] = 0;   // self-reset for next replay
        int cnt = dg < CAP ? dg : CAP;
        const int* sl = g_slot + (size_t)node * CAP;

        float a0 = 0.f, a1 = 0.f;
        int k = 0;
        for (; k + 8 <= cnt; k += 8) {
            int s[8];
            #pragma unroll
            for (int u = 0; u < 8; u++) s[u] = sl[k + u];
            float x[8], y[8];
            #pragma unroll
            for (int u = 0; u < 8; u++) {
                const float* r = h + (size_t)s[u] * D;
                x[u] = r[lane];
                y[u] = r[lane + 32];
            }
            a0 += ((x[0] + x[1]) + (x[2] + x[3])) + ((x[4] + x[5]) + (x[6] + x[7]));
            a1 += ((y[0] + y[1]) + (y[2] + y[3])) + ((y[4] + y[5]) + (y[6] + y[7]));
        }
        for (; k + 2 <= cnt; k += 2) {
            const float* r0 = h + (size_t)sl[k] * D;
            const float* r1 = h + (size_t)sl[k + 1] * D;
            float x0 = r0[lane], x1 = r1[lane];
            float y0 = r0[lane + 32], y1 = r1[lane + 32];
            a0 += x0 + x1;
            a1 += y0 + y1;
        }
        if (k < cnt) {
            const float* r0 = h + (size_t)sl[k] * D;
            a0 += r0[lane];
            a1 += r0[lane + 32];
        }
        float inv = 1.0f / fmaxf((float)dg, 1.0f);
        ht[m][64 + lane]      = a0 * inv;
        ht[m][64 + lane + 32] = a1 * inv;
    }
    __syncthreads();

    // Phase B: GEMM. thread (tx,ty) computes 4 nodes x 4 outputs.
    int tx = t & 15;
    int ty = t >> 4;
    int j0 = tx * 4;
    int m0 = ty * 4;

    float4 bv = *(const float4*)(b + j0);
    float acc[4][4];
    #pragma unroll
    for (int i = 0; i < 4; i++) {
        acc[i][0] = bv.x; acc[i][1] = bv.y; acc[i][2] = bv.z; acc[i][3] = bv.w;
    }

    #pragma unroll 4
    for (int k = 0; k < DK; k++) {
        float4 wv = *(const float4*)&Ws[k * D + j0];
        float a0 = ht[m0 + 0][k];
        float a1 = ht[m0 + 1][k];
        float a2 = ht[m0 + 2][k];
        float a3 = ht[m0 + 3][k];
        acc[0][0] = fmaf(a0, wv.x, acc[0][0]);
        acc[0][1] = fmaf(a0, wv.y, acc[0][1]);
        acc[0][2] = fmaf(a0, wv.z, acc[0][2]);
        acc[0][3] = fmaf(a0, wv.w, acc[0][3]);
        acc[1][0] = fmaf(a1, wv.x, acc[1][0]);
        acc[1][1] = fmaf(a1, wv.y, acc[1][1]);
        acc[1][2] = fmaf(a1, wv.z, acc[1][2]);
        acc[1][3] = fmaf(a1, wv.w, acc[1][3]);
        acc[2][0] = fmaf(a2, wv.x, acc[2][0]);
        acc[2][1] = fmaf(a2, wv.y, acc[2][1]);
        acc[2][2] = fmaf(a2, wv.z, acc[2][2]);
        acc[2][3] = fmaf(a2, wv.w, acc[2][3]);
        acc[3][0] = fmaf(a3, wv.x, acc[3][0]);
        acc[3][1] = fmaf(a3, wv.y, acc[3][1]);
        acc[3][2] = fmaf(a3, wv.z, acc[3][2]);
        acc[3][3] = fmaf(a3, wv.w, acc[3][3]);
    }

    #pragma unroll
    for (int i = 0; i < 4; i++) {
        int node = base + m0 + i;
        if (node < NN) {
            float4 o = make_float4(acc[i][0], acc[i][1], acc[i][2], acc[i][3]);
            *(float4*)(out + (size_t)node * D + j0) = o;
        }
    }
}

// ---------------------------------------------------------------------------
// Launch
// ---------------------------------------------------------------------------
extern "C" void kernel_launch(void* const* d_in, const int* in_sizes, int n_in,
                              void* d_out, int out_size) {
    const float* h   = (const float*)d_in[0];
    const int*   src = (const int*)d_in[1];
    const int*   dst = (const int*)d_in[2];
    const float* W   = (const float*)d_in[3];
    const float* b   = (const float*)d_in[4];
    float* out = (float*)d_out;

    fill_kernel<<<(NE / 4 + 255) / 256, 256>>>(src, dst);
    fused_kernel<<<(NN + 63) / 64, 256>>>(h, W, b, out);
}

// round 7
// speedup vs baseline: 1.0449x; 1.0449x over previous
#include <cuda_runtime.h>
#include <cuda_bf16.h>
#include <cstdint>

#define NN 50000
#define NE 800000
#define D  64
#define DK 128
#define CAP 96
#define HT_STRIDE 132

// Statically zero-initialized; fused_kernel resets each node's counter after
// reading it, so every graph replay starts from zeroed counters.
__device__ int g_deg_i[NN];
__device__ int g_slot[(size_t)NN * CAP];

// ---------------------------------------------------------------------------
// Kernel 1: bucket fill. 4 edges per thread via int4 loads.
// ---------------------------------------------------------------------------
__global__ __launch_bounds__(256) void fill_kernel(const int* __restrict__ src,
                                                   const int* __restrict__ dst) {
    int q = blockIdx.x * blockDim.x + threadIdx.x;
    if (q >= NE / 4) return;
    int4 s4 = ((const int4*)src)[q];
    int4 d4 = ((const int4*)dst)[q];
    int pos;
    pos = atomicAdd(&g_deg_i[d4.x], 1); if (pos < CAP) g_slot[(size_t)d4.x * CAP + pos] = s4.x;
    pos = atomicAdd(&g_deg_i[d4.y], 1); if (pos < CAP) g_slot[(size_t)d4.y * CAP + pos] = s4.y;
    pos = atomicAdd(&g_deg_i[d4.z], 1); if (pos < CAP) g_slot[(size_t)d4.z * CAP + pos] = s4.z;
    pos = atomicAdd(&g_deg_i[d4.w], 1); if (pos < CAP) g_slot[(size_t)d4.w * CAP + pos] = s4.w;
}

// ---------------------------------------------------------------------------
// Kernel 2: fused gather + GEMM.
// Gather: warp loads ALL slot indices for a node with ONE coalesced load,
// broadcasts via shfl -> feature loads have no index-load on their critical
// path (32 loads in flight).
// ---------------------------------------------------------------------------
__global__ __launch_bounds__(256) void fused_kernel(const float* __restrict__ h,
                                                    const float* __restrict__ W,
                                                    const float* __restrict__ b,
                                                    float* __restrict__ out) {
    __shared__ float Ws[DK * D];          // 32 KB
    __shared__ float ht[64][HT_STRIDE];   // ~33.8 KB

    int t = threadIdx.x;
    int base = blockIdx.x * 64;
    int warp = t >> 5;
    int lane = t & 31;

    // Stage W
    {
        const float4* Wv = (const float4*)W;
        float4* Wsv = (float4*)Ws;
        #pragma unroll
        for (int i = 0; i < 8; i++) Wsv[t + i * 256] = Wv[t + i * 256];
    }

    // Phase A: gather. Warp w handles nodes base + w*8 .. +7.
    #pragma unroll 1
    for (int i = 0; i < 8; i++) {
        int m = warp * 8 + i;
        int node = base + m;
        if (node >= NN) break;

        const float* hrow = h + (size_t)node * D;
        ht[m][lane]      = hrow[lane];
        ht[m][lane + 32] = hrow[lane + 32];

        int dg = g_deg_i[node];
        if (lane == 0) g_deg_i[node] = 0;   // self-reset for next replay
        int cnt = dg < CAP ? dg : CAP;
        const int* sl = g_slot + (size_t)node * CAP;

        float a0 = 0.f, a1 = 0.f, c0 = 0.f, c1 = 0.f;

        #pragma unroll 1
        for (int kb = 0; kb < cnt; kb += 32) {
            int nk = cnt - kb; if (nk > 32) nk = 32;
            // ONE coalesced load fetches up to 32 slot indices
            int sv = (lane < nk) ? sl[kb + lane] : 0;
            int k = 0;
            #pragma unroll 1
            for (; k + 4 <= nk; k += 4) {
                int s0 = __shfl_sync(0xffffffffu, sv, k);
                int s1 = __shfl_sync(0xffffffffu, sv, k + 1);
                int s2 = __shfl_sync(0xffffffffu, sv, k + 2);
                int s3 = __shfl_sync(0xffffffffu, sv, k + 3);
                const float* r0 = h + (size_t)s0 * D;
                const float* r1 = h + (size_t)s1 * D;
                const float* r2 = h + (size_t)s2 * D;
                const float* r3 = h + (size_t)s3 * D;
                float x0 = r0[lane],      x1 = r1[lane],      x2 = r2[lane],      x3 = r3[lane];
                float y0 = r0[lane + 32], y1 = r1[lane + 32], y2 = r2[lane + 32], y3 = r3[lane + 32];
                a0 += x0; c0 += x1; a0 += x2; c0 += x3;
                a1 += y0; c1 += y1; a1 += y2; c1 += y3;
            }
            for (; k < nk; k++) {
                int s0 = __shfl_sync(0xffffffffu, sv, k);
                const float* r0 = h + (size_t)s0 * D;
                a0 += r0[lane];
                a1 += r0[lane + 32];
            }
        }

        float inv = 1.0f / fmaxf((float)dg, 1.0f);
        ht[m][64 + lane]      = (a0 + c0) * inv;
        ht[m][64 + lane + 32] = (a1 + c1) * inv;
    }
    __syncthreads();

    // Phase B: GEMM. thread (tx,ty) computes 4 nodes x 4 outputs.
    int tx = t & 15;
    int ty = t >> 4;
    int j0 = tx * 4;
    int m0 = ty * 4;

    float4 bv = *(const float4*)(b + j0);
    float acc[4][4];
    #pragma unroll
    for (int i = 0; i < 4; i++) {
        acc[i][0] = bv.x; acc[i][1] = bv.y; acc[i][2] = bv.z; acc[i][3] = bv.w;
    }

    #pragma unroll 4
    for (int k = 0; k < DK; k++) {
        float4 wv = *(const float4*)&Ws[k * D + j0];
        float a0 = ht[m0 + 0][k];
        float a1 = ht[m0 + 1][k];
        float a2 = ht[m0 + 2][k];
        float a3 = ht[m0 + 3][k];
        acc[0][0] = fmaf(a0, wv.x, acc[0][0]);
        acc[0][1] = fmaf(a0, wv.y, acc[0][1]);
        acc[0][2] = fmaf(a0, wv.z, acc[0][2]);
        acc[0][3] = fmaf(a0, wv.w, acc[0][3]);
        acc[1][0] = fmaf(a1, wv.x, acc[1][0]);
        acc[1][1] = fmaf(a1, wv.y, acc[1][1]);
        acc[1][2] = fmaf(a1, wv.z, acc[1][2]);
        acc[1][3] = fmaf(a1, wv.w, acc[1][3]);
        acc[2][0] = fmaf(a2, wv.x, acc[2][0]);
        acc[2][1] = fmaf(a2, wv.y, acc[2][1]);
        acc[2][2] = fmaf(a2, wv.z, acc[2][2]);
        acc[2][3] = fmaf(a2, wv.w, acc[2][3]);
        acc[3][0] = fmaf(a3, wv.x, acc[3][0]);
        acc[3][1] = fmaf(a3, wv.y, acc[3][1]);
        acc[3][2] = fmaf(a3, wv.z, acc[3][2]);
        acc[3][3] = fmaf(a3, wv.w, acc[3][3]);
    }

    #pragma unroll
    for (int i = 0; i < 4; i++) {
        int node = base + m0 + i;
        if (node < NN) {
            float4 o = make_float4(acc[i][0], acc[i][1], acc[i][2], acc[i][3]);
            *(float4*)(out + (size_t)node * D + j0) = o;
        }
    }
}

// ---------------------------------------------------------------------------
// Launch
// ---------------------------------------------------------------------------
extern "C" void kernel_launch(void* const* d_in, const int* in_sizes, int n_in,
                              void* d_out, int out_size) {
    const float* h   = (const float*)d_in[0];
    const int*   src = (const int*)d_in[1];
    const int*   dst = (const int*)d_in[2];
    const float* W   = (const float*)d_in[3];
    const float* b   = (const float*)d_in[4];
    float* out = (float*)d_out;

    fill_kernel<<<(NE / 4 + 255) / 256, 256>>>(src, dst);
    fused_kernel<<<(NN + 63) / 64, 256>>>(h, W, b, out);
}

// round 8
// speedup vs baseline: 2.0856x; 1.9960x over previous
#include <cuda_runtime.h>
#include <cuda_bf16.h>
#include <cstdint>

#define NN 50000
#define NE 800000
#define D  64
#define DK 128
#define CAP 96
#define HT_STRIDE 132

// Statically zero-initialized; fused_kernel resets counters (post-gather),
// so every graph replay starts from zeroed counters.
__device__ int g_deg_i[NN];
__device__ int g_slot[(size_t)NN * CAP];

// ---------------------------------------------------------------------------
// Kernel 1: bucket fill. 4 edges per thread via int4 loads.
// ---------------------------------------------------------------------------
__global__ __launch_bounds__(256) void fill_kernel(const int* __restrict__ src,
                                                   const int* __restrict__ dst) {
    int q = blockIdx.x * blockDim.x + threadIdx.x;
    if (q >= NE / 4) return;
    int4 s4 = ((const int4*)src)[q];
    int4 d4 = ((const int4*)dst)[q];
    int pos;
    pos = atomicAdd(&g_deg_i[d4.x], 1); if (pos < CAP) g_slot[(size_t)d4.x * CAP + pos] = s4.x;
    pos = atomicAdd(&g_deg_i[d4.y], 1); if (pos < CAP) g_slot[(size_t)d4.y * CAP + pos] = s4.y;
    pos = atomicAdd(&g_deg_i[d4.z], 1); if (pos < CAP) g_slot[(size_t)d4.z * CAP + pos] = s4.z;
    pos = atomicAdd(&g_deg_i[d4.w], 1); if (pos < CAP) g_slot[(size_t)d4.w * CAP + pos] = s4.w;
}

// ---------------------------------------------------------------------------
// Kernel 2: fused gather + GEMM (R5-proven gather shape, float2-vectorized).
// ---------------------------------------------------------------------------
__global__ __launch_bounds__(256) void fused_kernel(const float* __restrict__ h,
                                                    const float* __restrict__ W,
                                                    const float* __restrict__ b,
                                                    float* __restrict__ out) {
    __shared__ float Ws[DK * D];          // 32 KB
    __shared__ float ht[64][HT_STRIDE];   // ~33.8 KB

    int t = threadIdx.x;
    int base = blockIdx.x * 64;
    int warp = t >> 5;
    int lane = t & 31;

    // Stage W
    {
        const float4* Wv = (const float4*)W;
        float4* Wsv = (float4*)Ws;
        #pragma unroll
        for (int i = 0; i < 8; i++) Wsv[t + i * 256] = Wv[t + i * 256];
    }

    const float2* h2 = (const float2*)h;   // row stride = 32 float2

    // Phase A: gather. Warp w handles nodes base + w*8 .. +7.
    #pragma unroll 1
    for (int i = 0; i < 8; i++) {
        int m = warp * 8 + i;
        int node = base + m;
        if (node >= NN) break;

        // self features (features 2*lane, 2*lane+1)
        float2 sv = h2[(size_t)node * 32 + lane];
        *(float2*)&ht[m][2 * lane] = sv;

        int dg  = g_deg_i[node];
        int cnt = dg < CAP ? dg : CAP;
        const int* sl = g_slot + (size_t)node * CAP;

        float2 a = make_float2(0.f, 0.f);
        float2 c = make_float2(0.f, 0.f);
        int k = 0;
        for (; k + 4 <= cnt; k += 4) {
            int s0 = sl[k], s1 = sl[k + 1], s2 = sl[k + 2], s3 = sl[k + 3];
            float2 v0 = h2[(size_t)s0 * 32 + lane];
            float2 v1 = h2[(size_t)s1 * 32 + lane];
            float2 v2 = h2[(size_t)s2 * 32 + lane];
            float2 v3 = h2[(size_t)s3 * 32 + lane];
            a.x += v0.x; a.y += v0.y;
            c.x += v1.x; c.y += v1.y;
            a.x += v2.x; a.y += v2.y;
            c.x += v3.x; c.y += v3.y;
        }
        for (; k < cnt; k++) {
            float2 v0 = h2[(size_t)sl[k] * 32 + lane];
            a.x += v0.x; a.y += v0.y;
        }

        float inv = 1.0f / fmaxf((float)dg, 1.0f);
        float2 mn = make_float2((a.x + c.x) * inv, (a.y + c.y) * inv);
        *(float2*)&ht[m][64 + 2 * lane] = mn;
    }
    __syncthreads();

    // Reset counters for the next graph replay (overlaps with GEMM below).
    if (t < 64) {
        int node = base + t;
        if (node < NN) g_deg_i[node] = 0;
    }

    // Phase B: GEMM. thread (tx,ty) computes 4 nodes x 4 outputs.
    int tx = t & 15;
    int ty = t >> 4;
    int j0 = tx * 4;
    int m0 = ty * 4;

    float4 bv = *(const float4*)(b + j0);
    float acc[4][4];
    #pragma unroll
    for (int i = 0; i < 4; i++) {
        acc[i][0] = bv.x; acc[i][1] = bv.y; acc[i][2] = bv.z; acc[i][3] = bv.w;
    }

    #pragma unroll 4
    for (int k = 0; k < DK; k++) {
        float4 wv = *(const float4*)&Ws[k * D + j0];
        float a0 = ht[m0 + 0][k];
        float a1 = ht[m0 + 1][k];
        float a2 = ht[m0 + 2][k];
        float a3 = ht[m0 + 3][k];
        acc[0][0] = fmaf(a0, wv.x, acc[0][0]);
        acc[0][1] = fmaf(a0, wv.y, acc[0][1]);
        acc[0][2] = fmaf(a0, wv.z, acc[0][2]);
        acc[0][3] = fmaf(a0, wv.w, acc[0][3]);
        acc[1][0] = fmaf(a1, wv.x, acc[1][0]);
        acc[1][1] = fmaf(a1, wv.y, acc[1][1]);
        acc[1][2] = fmaf(a1, wv.z, acc[1][2]);
        acc[1][3] = fmaf(a1, wv.w, acc[1][3]);
        acc[2][0] = fmaf(a2, wv.x, acc[2][0]);
        acc[2][1] = fmaf(a2, wv.y, acc[2][1]);
        acc[2][2] = fmaf(a2, wv.z, acc[2][2]);
        acc[2][3] = fmaf(a2, wv.w, acc[2][3]);
        acc[3][0] = fmaf(a3, wv.x, acc[3][0]);
        acc[3][1] = fmaf(a3, wv.y, acc[3][1]);
        acc[3][2] = fmaf(a3, wv.z, acc[3][2]);
        acc[3][3] = fmaf(a3, wv.w, acc[3][3]);
    }

    #pragma unroll
    for (int i = 0; i < 4; i++) {
        int node = base + m0 + i;
        if (node < NN) {
            float4 o = make_float4(acc[i][0], acc[i][1], acc[i][2], acc[i][3]);
            *(float4*)(out + (size_t)node * D + j0) = o;
        }
    }
}

// ---------------------------------------------------------------------------
// Launch
// ---------------------------------------------------------------------------
extern "C" void kernel_launch(void* const* d_in, const int* in_sizes, int n_in,
                              void* d_out, int out_size) {
    const float* h   = (const float*)d_in[0];
    const int*   src = (const int*)d_in[1];
    const int*   dst = (const int*)d_in[2];
    const float* W   = (const float*)d_in[3];
    const float* b   = (const float*)d_in[4];
    float* out = (float*)d_out;

    fill_kernel<<<(NE / 4 + 255) / 256, 256>>>(src, dst);
    fused_kernel<<<(NN + 63) / 64, 256>>>(h, W, b, out);
}